// round 11
// baseline (speedup 1.0000x reference)
#include <cuda_runtime.h>
#include <cuda_bf16.h>
#include <cstdint>

// B=1024, S=200, D=64, C=256
// Inputs: rq_item_embeddings f32 [B,S,D], labels i32 [B,S], attention_mask i32 [B,S]
// Output (float32, concatenated):
//   [0 .. B*C*D)             cluster_emb
//   [B*C*D .. +B*C*S)        cluster_mask (0.0f/1.0f)
//
// Grid = B*8: each CTA owns one batch b and a 32-cluster range.
// Mask values are computed inline from smem labels (single write per byte,
// no zero-fill/ones ordering). 2 block barriers total.

namespace {
constexpr int B = 1024;
constexpr int S = 200;
constexpr int D = 64;
constexpr int C = 256;
constexpr int SPLIT = 8;
constexpr int CPART = C / SPLIT;      // 32 clusters per CTA
}

__global__ __launch_bounds__(256) void s3rec_fused_kernel(
    const float* __restrict__ x,       // [B,S,D]
    const int*   __restrict__ labels,  // [B,S]
    const int*   __restrict__ amask,   // [B,S]
    float*       __restrict__ out)
{
    __shared__ __align__(16) int lab[200];        // fused label+mask (-1 = masked)
    __shared__ int cnt[CPART];                    // per-local-cluster count
    __shared__ unsigned char bucket[CPART][S];    // member s-indices, 6.4 KB

    const int b    = blockIdx.x >> 3;
    const int part = blockIdx.x & 7;    // cluster octant
    const int tid  = threadIdx.x;
    const int w    = tid >> 5;
    const int lane = tid & 31;
    const int cBase = part * CPART;

    float* maskOutP = out + (size_t)B * C * D
                          + (size_t)b * C * S
                          + (size_t)cBase * S;

    // ---- Phase 0: wide parallel label load ----------------------------
    int myLab = -1;
    if (tid < S) {
        int m = __ldg(amask + b * S + tid);
        myLab = m ? __ldg(labels + b * S + tid) : -1;
        lab[tid] = myLab;
    }
    if (tid < CPART) cnt[tid] = 0;
    __syncthreads();

    // ---- Phase 1a: bucket scatter (count + slot from one atomic) ------
    {
        const int cl = myLab - cBase;
        if (cl >= 0 && cl < CPART) {
            int p = atomicAdd(&cnt[cl], 1);
            bucket[cl][p] = (unsigned char)tid;
        }
    }

    // ---- Phase 1b: mask compute-store (single write per byte) ---------
    {
        float4* mq = reinterpret_cast<float4*>(maskOutP);
        constexpr int QPC = S / 4;          // 50 quads per cluster row
        constexpr int NQ  = CPART * QPC;    // 1600
        #pragma unroll 7
        for (int i = tid; i < NQ; i += 256) {
            const int cl = i / QPC;                 // compiler -> mul-shift
            const int s0 = (i - cl * QPC) * 4;
            const int4 l4 = *reinterpret_cast<const int4*>(&lab[s0]);
            const int cg = cBase + cl;
            float4 v;
            v.x = (l4.x == cg) ? 1.0f : 0.0f;
            v.y = (l4.y == cg) ? 1.0f : 0.0f;
            v.z = (l4.z == cg) ? 1.0f : 0.0f;
            v.w = (l4.w == cg) ? 1.0f : 0.0f;
            __stcs(mq + i, v);
        }
    }
    __syncthreads();

    // ---- Phase 2: gather; half-warp per cluster, float4 lanes ---------
    {
        const float* xb = x + (size_t)b * S * D;
        float* embOut   = out + (size_t)b * C * D;
        const int hw  = lane >> 4;          // half-warp id (0/1)
        const int l16 = lane & 15;

        #pragma unroll
        for (int pass = 0; pass < CPART / 16; pass++) {   // 2 passes
            const int cLocal = pass * 16 + w * 2 + hw;
            const int k = cnt[cLocal];
            float4 acc = make_float4(0.f, 0.f, 0.f, 0.f);
            if (k > 0) {
                int sCur = bucket[cLocal][0];
                for (int j = 0; j < k; j++) {
                    const int sNext = (j + 1 < k) ? (int)bucket[cLocal][j + 1] : 0;
                    const float4 vv =
                        reinterpret_cast<const float4*>(xb + sCur * D)[l16];
                    acc.x += vv.x; acc.y += vv.y; acc.z += vv.z; acc.w += vv.w;
                    sCur = sNext;
                }
                const float inv = 1.0f / (float)k;
                acc.x *= inv; acc.y *= inv; acc.z *= inv; acc.w *= inv;
            }
            __stcs(reinterpret_cast<float4*>(embOut + (cBase + cLocal) * D) + l16, acc);
        }
    }
}

extern "C" void kernel_launch(void* const* d_in, const int* in_sizes, int n_in,
                              void* d_out, int out_size)
{
    const float* x      = (const float*)d_in[0];
    const int*   labels = (const int*)d_in[1];
    const int*   amask  = (const int*)d_in[2];
    float*       out    = (float*)d_out;

    s3rec_fused_kernel<<<B * SPLIT, 256>>>(x, labels, amask, out);
}

// round 12
// speedup vs baseline: 1.0007x; 1.0007x over previous
#include <cuda_runtime.h>
#include <cuda_bf16.h>
#include <cstdint>

// B=1024, S=200, D=64, C=256
// Inputs: rq_item_embeddings f32 [B,S,D], labels i32 [B,S], attention_mask i32 [B,S]
// Output (float32, concatenated):
//   [0 .. B*C*D)             cluster_emb
//   [B*C*D .. +B*C*S)        cluster_mask (0.0f/1.0f)
//
// Grid = B*16, block = 128: each CTA owns one batch b and a 16-cluster range.
// R10 structure (zero-fill + ones scatter + uint8 buckets, 2 barriers) at
// finer CTA granularity: cheaper barriers, more independent phase pipelines
// per SM.

namespace {
constexpr int B = 1024;
constexpr int S = 200;
constexpr int D = 64;
constexpr int C = 256;
constexpr int SPLIT = 16;
constexpr int CPART = C / SPLIT;      // 16 clusters per CTA
constexpr int NTHR  = 128;
}

__global__ __launch_bounds__(NTHR) void s3rec_fused_kernel(
    const float* __restrict__ x,       // [B,S,D]
    const int*   __restrict__ labels,  // [B,S]
    const int*   __restrict__ amask,   // [B,S]
    float*       __restrict__ out)
{
    __shared__ int cnt[CPART];                    // per-local-cluster count
    __shared__ unsigned char bucket[CPART][S];    // member s-indices, 3.2 KB

    const int b    = blockIdx.x >> 4;
    const int part = blockIdx.x & 15;   // cluster 16th
    const int tid  = threadIdx.x;
    const int w    = tid >> 5;          // 0..3
    const int lane = tid & 31;
    const int cBase = part * CPART;

    float* maskOutP = out + (size_t)B * C * D
                          + (size_t)b * C * S
                          + (size_t)cBase * S;

    // ---- Phase 0: label load (2 rounds) + counts zero + mask zero-fill
    int lab0 = -1, lab1 = -1;
    {
        int m0 = __ldg(amask + b * S + tid);
        lab0 = m0 ? __ldg(labels + b * S + tid) : -1;
        const int s1 = tid + NTHR;                 // 128..255; valid if < 200
        if (s1 < S) {
            int m1 = __ldg(amask + b * S + s1);
            lab1 = m1 ? __ldg(labels + b * S + s1) : -1;
        }
    }
    if (tid < CPART) cnt[tid] = 0;

    {
        const float4 z4 = make_float4(0.f, 0.f, 0.f, 0.f);
        float4* mq = reinterpret_cast<float4*>(maskOutP);
        constexpr int NQ = CPART * S / 4;   // 800 quads, 6.25/thread
        #pragma unroll 7
        for (int i = tid; i < NQ; i += NTHR)
            __stcs(mq + i, z4);
    }
    __syncthreads();

    // ---- Phase 1: bucket scatter + ones write (one atomic does both) --
    {
        const int cl0 = lab0 - cBase;
        if (cl0 >= 0 && cl0 < CPART) {
            int p = atomicAdd(&cnt[cl0], 1);
            bucket[cl0][p] = (unsigned char)tid;
            maskOutP[cl0 * S + tid] = 1.0f;
        }
        const int s1 = tid + NTHR;
        const int cl1 = lab1 - cBase;
        if (s1 < S && cl1 >= 0 && cl1 < CPART) {
            int p = atomicAdd(&cnt[cl1], 1);
            bucket[cl1][p] = (unsigned char)s1;
            maskOutP[cl1 * S + s1] = 1.0f;
        }
    }
    __syncthreads();

    // ---- Phase 2: gather; half-warp per cluster, float4 lanes ---------
    // 4 warps x 2 half-warps = 8 clusters per pass, 2 passes = 16.
    {
        const float* xb = x + (size_t)b * S * D;
        float* embOut   = out + (size_t)b * C * D;
        const int hw  = lane >> 4;          // half-warp id (0/1)
        const int l16 = lane & 15;

        #pragma unroll
        for (int pass = 0; pass < CPART / 8; pass++) {   // 2 passes
            const int cLocal = pass * 8 + w * 2 + hw;
            const int k = cnt[cLocal];
            float4 acc = make_float4(0.f, 0.f, 0.f, 0.f);
            if (k > 0) {
                int sCur = bucket[cLocal][0];
                for (int j = 0; j < k; j++) {
                    const int sNext = (j + 1 < k) ? (int)bucket[cLocal][j + 1] : 0;
                    const float4 vv =
                        reinterpret_cast<const float4*>(xb + sCur * D)[l16];
                    acc.x += vv.x; acc.y += vv.y; acc.z += vv.z; acc.w += vv.w;
                    sCur = sNext;
                }
                const float inv = 1.0f / (float)k;
                acc.x *= inv; acc.y *= inv; acc.z *= inv; acc.w *= inv;
            }
            __stcs(reinterpret_cast<float4*>(embOut + (cBase + cLocal) * D) + l16, acc);
        }
    }
}

extern "C" void kernel_launch(void* const* d_in, const int* in_sizes, int n_in,
                              void* d_out, int out_size)
{
    const float* x      = (const float*)d_in[0];
    const int*   labels = (const int*)d_in[1];
    const int*   amask  = (const int*)d_in[2];
    float*       out    = (float*)d_out;

    s3rec_fused_kernel<<<B * SPLIT, NTHR>>>(x, labels, amask, out);
}